// round 1
// baseline (speedup 1.0000x reference)
#include <cuda_runtime.h>
#include <cuda_bf16.h>
#include <math.h>

// ---------------- problem constants ----------------
#define NN      50000
#define NPREV   50000
#define NFEATS  256
#define NHID    256
#define NHEADS  4
#define HD      64
#define DEG_IN  16
#define DEG_C   8
#define ALPHA   0.2f

// ---------------- device scratch (static, allowed) ----------------
__device__ float d_Wh  [NN * NHID];      // intra Wh (with bias)
__device__ float d_x   [NN * NHID];      // intra GAT output
__device__ float d_Whp [NPREV * NHID];   // cross W @ h_prev
__device__ float d_Whx [NN * NHID];      // cross W @ x
__device__ float d_h   [NN * NHID];      // 0.5*(h_c + h_s)
__device__ float d_gi  [NN * 3 * NHID];
__device__ float d_gh  [NN * 3 * NHID];

__device__ float d_pk_intra[NFEATS * NHID];   // [K=256, N=256]
__device__ float d_pk_cross[NHID * NHID];     // [256, 256]
__device__ float d_pk_ih  [NHID * 3 * NHID];  // [256, 768]
__device__ float d_pk_hh  [NHID * 3 * NHID];  // [256, 768]

__device__ float d_es [NN * NHEADS];
__device__ float d_ed [NN * NHEADS];
__device__ float d_esP[NPREV * NHEADS];
__device__ float d_edX[NN * NHEADS];

// ---------------- weight packing ----------------
// W[h][f][d]  ->  out[f][h*HD+d]   (so GEMM B is row-major [K=256, N=256])
__global__ void pack_headwise(const float* __restrict__ W, float* __restrict__ out) {
    int idx = blockIdx.x * 256 + threadIdx.x;          // 0 .. 65535
    int c = idx & 255;                                 // output col
    int f = idx >> 8;                                  // k
    int h = c >> 6, dd = c & 63;
    out[idx] = W[(h * 256 + f) * 64 + dd];
}

// W[n][k] (768x256)  ->  out[k][n]  (B row-major [256, 768])
__global__ void pack_T(const float* __restrict__ W, float* __restrict__ out) {
    int idx = blockIdx.x * 256 + threadIdx.x;          // 0 .. 196607
    int k = idx / 768, n = idx % 768;
    out[idx] = W[n * 256 + k];
}

// ---------------- tiled fp32 GEMM: C = A[M,K] @ B[K,N] (+bias) ----------------
#define BM 128
#define BN 128
#define BKK 16

__global__ __launch_bounds__(256)
void sgemm(const float* __restrict__ A, const float* __restrict__ B,
           const float* __restrict__ bias, float* __restrict__ C,
           int M, int N, int K) {
    __shared__ __align__(16) float As[BKK][BM];
    __shared__ __align__(16) float Bs[BKK][BN];

    int bx = blockIdx.x;   // along N
    int by = blockIdx.y;   // along M
    int tid = threadIdx.x;
    int tx = tid & 15;     // 16 thread cols
    int ty = tid >> 4;     // 16 thread rows

    float acc[8][8];
    #pragma unroll
    for (int m = 0; m < 8; m++)
        #pragma unroll
        for (int n = 0; n < 8; n++) acc[m][n] = 0.f;

    for (int k0 = 0; k0 < K; k0 += BKK) {
        #pragma unroll
        for (int t = 0; t < 2; t++) {
            int v = tid + t * 256;
            // A tile: 128 rows x 16 k, as 512 float4 along K
            int r  = v >> 2, kq = v & 3;
            int row = by * BM + r;
            float4 av = make_float4(0.f, 0.f, 0.f, 0.f);
            if (row < M)
                av = *(const float4*)&A[row * K + k0 + kq * 4];
            As[kq * 4 + 0][r] = av.x;
            As[kq * 4 + 1][r] = av.y;
            As[kq * 4 + 2][r] = av.z;
            As[kq * 4 + 3][r] = av.w;
            // B tile: 16 k x 128 cols, as 512 float4 along N
            int kr = v >> 5, cq = v & 31;
            *(float4*)&Bs[kr][cq * 4] =
                *(const float4*)&B[(k0 + kr) * N + bx * BN + cq * 4];
        }
        __syncthreads();

        #pragma unroll
        for (int k = 0; k < BKK; k++) {
            float ra[8], rb[8];
            *(float4*)&ra[0] = *(float4*)&As[k][ty * 8];
            *(float4*)&ra[4] = *(float4*)&As[k][ty * 8 + 4];
            *(float4*)&rb[0] = *(float4*)&Bs[k][tx * 8];
            *(float4*)&rb[4] = *(float4*)&Bs[k][tx * 8 + 4];
            #pragma unroll
            for (int m = 0; m < 8; m++)
                #pragma unroll
                for (int n = 0; n < 8; n++)
                    acc[m][n] = fmaf(ra[m], rb[n], acc[m][n]);
        }
        __syncthreads();
    }

    int col0 = bx * BN + tx * 8;
    #pragma unroll
    for (int m = 0; m < 8; m++) {
        int row = by * BM + ty * 8 + m;
        if (row >= M) continue;
        #pragma unroll
        for (int n4 = 0; n4 < 8; n4 += 4) {
            float4 v;
            v.x = acc[m][n4 + 0];
            v.y = acc[m][n4 + 1];
            v.z = acc[m][n4 + 2];
            v.w = acc[m][n4 + 3];
            if (bias) {
                v.x += bias[col0 + n4 + 0];
                v.y += bias[col0 + n4 + 1];
                v.z += bias[col0 + n4 + 2];
                v.w += bias[col0 + n4 + 3];
            }
            *(float4*)&C[row * N + col0 + n4] = v;
        }
    }
}

// ---------------- per-(node,head) attention logit dots ----------------
// s1 = dot(Wh[n,h,:], a[h, 0:64]),  s2 = dot(Wh[n,h,:], a[h, 64:128])
__global__ void dots_kernel(const float* __restrict__ Wh, const float* __restrict__ a,
                            float* __restrict__ es, float* __restrict__ ed, int n) {
    int warp = threadIdx.x >> 5;
    int lane = threadIdx.x & 31;
    int node = blockIdx.x * 2 + (warp >> 2);
    int h = warp & 3;
    if (node >= n) return;
    const float* row = Wh + node * NHID + h * HD;
    float v0 = row[lane], v1 = row[lane + 32];
    const float* ah = a + h * 128;
    float s1 = fmaf(v0, ah[lane], v1 * ah[lane + 32]);
    float s2 = fmaf(v0, ah[64 + lane], v1 * ah[96 + lane]);
    #pragma unroll
    for (int off = 16; off > 0; off >>= 1) {
        s1 += __shfl_down_sync(0xffffffffu, s1, off);
        s2 += __shfl_down_sync(0xffffffffu, s2, off);
    }
    if (lane == 0) {
        if (es) es[node * NHEADS + h] = s1;
        if (ed) ed[node * NHEADS + h] = s2;
    }
}

// ---------------- intra-turn GAT aggregation (deg 16) ----------------
__global__ __launch_bounds__(256)
void intra_agg(const float* __restrict__ Wh, const float* __restrict__ es,
               const float* __restrict__ ed, const float* __restrict__ ab,
               const int* __restrict__ src, float* __restrict__ x) {
    int d = blockIdx.x;
    int tid = threadIdx.x;
    __shared__ int   s_src[DEG_IN];
    __shared__ float se[NHEADS * DEG_IN];   // [h*16 + i]

    if (tid < DEG_IN) s_src[tid] = src[d * DEG_IN + tid];
    __syncthreads();

    if (tid < NHEADS * DEG_IN) {
        int i = tid & 15, h = tid >> 4;
        float e = es[s_src[i] * NHEADS + h] + ed[d * NHEADS + h] + ab[h];
        se[tid] = (e >= 0.f) ? e : ALPHA * e;
    }
    __syncthreads();

    if (tid < NHEADS) {
        float m = -1e30f;
        #pragma unroll
        for (int i = 0; i < DEG_IN; i++) m = fmaxf(m, se[tid * DEG_IN + i]);
        float s = 0.f;
        #pragma unroll
        for (int i = 0; i < DEG_IN; i++) {
            float ex = expf(se[tid * DEG_IN + i] - m);
            se[tid * DEG_IN + i] = ex;
            s += ex;
        }
        float inv = 1.f / fmaxf(s, 1e-9f);
        #pragma unroll
        for (int i = 0; i < DEG_IN; i++) se[tid * DEG_IN + i] *= inv;
    }
    __syncthreads();

    int h = tid >> 6;
    float acc = 0.f;
    #pragma unroll
    for (int i = 0; i < DEG_IN; i++)
        acc = fmaf(se[h * DEG_IN + i], Wh[s_src[i] * NHID + tid], acc);
    x[d * NHID + tid] = acc;
}

// ---------------- cross-turn GAT (counter + support fused, deg 8 each) ----------------
__global__ __launch_bounds__(256)
void cross_agg(const float* __restrict__ Whp, const float* __restrict__ esP,
               const float* __restrict__ edX, const int* __restrict__ src_c,
               const int* __restrict__ src_s, float* __restrict__ hout) {
    int d = blockIdx.x;
    int tid = threadIdx.x;
    __shared__ int   sc[DEG_C], ss[DEG_C];
    __shared__ float se[2 * NHEADS * DEG_C];   // [which*32 + h*8 + i]

    if (tid < DEG_C)                sc[tid]          = src_c[d * DEG_C + tid];
    else if (tid < 2 * DEG_C)       ss[tid - DEG_C]  = src_s[d * DEG_C + (tid - DEG_C)];
    __syncthreads();

    if (tid < 64) {
        int which = tid >> 5;
        int t = tid & 31;
        int i = t & 7, h = t >> 3;
        int s = which ? ss[i] : sc[i];
        float e = esP[s * NHEADS + h] + edX[d * NHEADS + h];
        se[tid] = (e >= 0.f) ? e : ALPHA * e;
    }
    __syncthreads();

    if (tid < 8) {
        float* ep = &se[(tid >> 2) * 32 + (tid & 3) * 8];
        float m = -1e30f;
        #pragma unroll
        for (int i = 0; i < DEG_C; i++) m = fmaxf(m, ep[i]);
        float s = 0.f;
        #pragma unroll
        for (int i = 0; i < DEG_C; i++) { float ex = expf(ep[i] - m); ep[i] = ex; s += ex; }
        float inv = 1.f / fmaxf(s, 1e-9f);
        #pragma unroll
        for (int i = 0; i < DEG_C; i++) ep[i] *= inv;
    }
    __syncthreads();

    int h = tid >> 6;
    float acc = 0.f;
    #pragma unroll
    for (int i = 0; i < DEG_C; i++)
        acc = fmaf(se[h * DEG_C + i], Whp[sc[i] * NHID + tid], acc);
    #pragma unroll
    for (int i = 0; i < DEG_C; i++)
        acc = fmaf(se[32 + h * DEG_C + i], Whp[ss[i] * NHID + tid], acc);
    hout[d * NHID + tid] = 0.5f * acc;
}

// ---------------- GRU elementwise ----------------
__global__ void gru_kernel(const float* __restrict__ gi, const float* __restrict__ gh,
                           const float* __restrict__ h, float* __restrict__ out) {
    int idx = blockIdx.x * 256 + threadIdx.x;
    int node = idx >> 8, c = idx & 255;
    const float* gip = gi + node * 768;
    const float* ghp = gh + node * 768;
    float r = 1.f / (1.f + expf(-(gip[c]       + ghp[c])));
    float z = 1.f / (1.f + expf(-(gip[256 + c] + ghp[256 + c])));
    float nn = tanhf(gip[512 + c] + r * ghp[512 + c]);
    out[idx] = (1.f - z) * nn + z * h[idx];
}

// ---------------- host launcher ----------------
extern "C" void kernel_launch(void* const* d_in, const int* in_sizes, int n_in,
                              void* d_out, int out_size) {
    const float* h_t      = (const float*)d_in[0];
    const float* h_prev   = (const float*)d_in[1];
    const float* W_intra  = (const float*)d_in[2];
    const float* b_intra  = (const float*)d_in[3];   // [4,64] == flat [256] in head-concat order
    const float* a_intra  = (const float*)d_in[4];
    const float* ab_intra = (const float*)d_in[5];
    const float* W_cross  = (const float*)d_in[6];
    const float* a_cross  = (const float*)d_in[7];
    const float* W_ih     = (const float*)d_in[8];
    const float* W_hh     = (const float*)d_in[9];
    const float* b_ih     = (const float*)d_in[10];
    const float* b_hh     = (const float*)d_in[11];
    const int*   src_in   = (const int*)d_in[12];
    // d_in[13] = dst_in (repeat(arange(N),16) — structure used implicitly)
    const int*   src_c    = (const int*)d_in[14];
    // d_in[15] = dst_c
    const int*   src_s    = (const int*)d_in[16];
    // d_in[17] = dst_s
    float* out = (float*)d_out;

    float *p_Wh, *p_x, *p_Whp, *p_Whx, *p_h, *p_gi, *p_gh;
    float *p_pki, *p_pkc, *p_pkih, *p_pkhh;
    float *p_es, *p_ed, *p_esP, *p_edX;
    cudaGetSymbolAddress((void**)&p_Wh,  d_Wh);
    cudaGetSymbolAddress((void**)&p_x,   d_x);
    cudaGetSymbolAddress((void**)&p_Whp, d_Whp);
    cudaGetSymbolAddress((void**)&p_Whx, d_Whx);
    cudaGetSymbolAddress((void**)&p_h,   d_h);
    cudaGetSymbolAddress((void**)&p_gi,  d_gi);
    cudaGetSymbolAddress((void**)&p_gh,  d_gh);
    cudaGetSymbolAddress((void**)&p_pki, d_pk_intra);
    cudaGetSymbolAddress((void**)&p_pkc, d_pk_cross);
    cudaGetSymbolAddress((void**)&p_pkih, d_pk_ih);
    cudaGetSymbolAddress((void**)&p_pkhh, d_pk_hh);
    cudaGetSymbolAddress((void**)&p_es,  d_es);
    cudaGetSymbolAddress((void**)&p_ed,  d_ed);
    cudaGetSymbolAddress((void**)&p_esP, d_esP);
    cudaGetSymbolAddress((void**)&p_edX, d_edX);

    // 1. pack weights
    pack_headwise<<<256, 256>>>(W_intra, p_pki);
    pack_headwise<<<256, 256>>>(W_cross, p_pkc);
    pack_T<<<768, 256>>>(W_ih, p_pkih);
    pack_T<<<768, 256>>>(W_hh, p_pkhh);

    dim3 g256(NHID / BN, (NN + BM - 1) / BM);         // (2, 391)
    dim3 g768(3 * NHID / BN, (NN + BM - 1) / BM);     // (6, 391)

    // 2. Wh = h_t @ Wintra + b_intra
    sgemm<<<g256, 256>>>(h_t, p_pki, b_intra, p_Wh, NN, NHID, NFEATS);
    // 3. attention logits (intra): es, ed
    dots_kernel<<<NN / 2, 256>>>(p_Wh, a_intra, p_es, p_ed, NN);
    // 4. intra GAT -> x
    intra_agg<<<NN, 256>>>(p_Wh, p_es, p_ed, ab_intra, src_in, p_x);
    // 5. cross projections
    sgemm<<<g256, 256>>>(h_prev, p_pkc, nullptr, p_Whp, NPREV, NHID, NHID);
    sgemm<<<g256, 256>>>(p_x,    p_pkc, nullptr, p_Whx, NN,    NHID, NHID);
    // 6. cross logits
    dots_kernel<<<NPREV / 2, 256>>>(p_Whp, a_cross, p_esP, nullptr, NPREV);
    dots_kernel<<<NN / 2,    256>>>(p_Whx, a_cross, nullptr, p_edX, NN);
    // 7. cross GAT (counter + support fused) -> h
    cross_agg<<<NN, 256>>>(p_Whp, p_esP, p_edX, src_c, src_s, p_h);
    // 8. GRU gate GEMMs
    sgemm<<<g768, 256>>>(p_x, p_pkih, b_ih, p_gi, NN, 3 * NHID, NHID);
    sgemm<<<g768, 256>>>(p_h, p_pkhh, b_hh, p_gh, NN, 3 * NHID, NHID);
    // 9. GRU elementwise -> out
    gru_kernel<<<NN, 256>>>(p_gi, p_gh, p_h, out);
}

// round 3
// speedup vs baseline: 2.1198x; 2.1198x over previous
#include <cuda_runtime.h>
#include <cuda_bf16.h>
#include <math.h>
#include <stdint.h>

// ---------------- problem constants ----------------
#define NN      50000
#define NPREV   50000
#define NFEATS  256
#define NHID    256
#define NHEADS  4
#define HD      64
#define DEG_IN  16
#define DEG_C   8
#define ALPHA   0.2f

// ---------------- device scratch ----------------
__device__ float d_Wh  [NN * NHID];
__device__ float d_x   [NN * NHID];
__device__ float d_Whp [NPREV * NHID];
__device__ float d_h   [NN * NHID];
__device__ float d_gi  [NN * 3 * NHID];
__device__ float d_gh  [NN * 3 * NHID];
__device__ float d_pk_intra[NHID * NFEATS];   // [n=256][k=256] row-major
__device__ float d_pk_cross[NHID * NHID];
__device__ float d_es [NN * NHEADS];
__device__ float d_ed [NN * NHEADS];
__device__ float d_esP[NPREV * NHEADS];
__device__ float d_edX[NN * NHEADS];

// ---------------- small helpers ----------------
__device__ __forceinline__ uint32_t smem_u32(const void* p) {
    uint32_t a;
    asm("{ .reg .u64 t; cvta.to.shared.u64 t, %1; cvt.u32.u64 %0, t; }" : "=r"(a) : "l"(p));
    return a;
}
__device__ __forceinline__ uint32_t f2tf32(float x) {
    uint32_t r;
    asm("cvt.rna.tf32.f32 %0, %1;" : "=r"(r) : "f"(x));
    return r;
}
__device__ __forceinline__ void cp16(uint32_t dst, const void* src) {
    asm volatile("cp.async.cg.shared.global [%0], [%1], 16;" :: "r"(dst), "l"(src));
}
__device__ __forceinline__ void cp_commit() {
    asm volatile("cp.async.commit_group;" ::: "memory");
}
template<int N>
__device__ __forceinline__ void cp_wait() {
    asm volatile("cp.async.wait_group %0;" :: "n"(N) : "memory");
}
__device__ __forceinline__ void mma_tf32(float* d, const uint32_t* a, const uint32_t* b) {
    asm volatile(
        "mma.sync.aligned.m16n8k8.row.col.f32.tf32.tf32.f32 "
        "{%0,%1,%2,%3},{%4,%5,%6,%7},{%8,%9},{%0,%1,%2,%3};"
        : "+f"(d[0]), "+f"(d[1]), "+f"(d[2]), "+f"(d[3])
        : "r"(a[0]), "r"(a[1]), "r"(a[2]), "r"(a[3]), "r"(b[0]), "r"(b[1]));
}

// ---------------- tensor-core GEMM via mma.sync (tf32) ----------------
// C[M, Nld] cols [n0, n0+128) = A[M,256] @ B[.,256]^T (B row-major [n][k]) + bias
// SPLIT=1: A split into tf32 hi+lo (2 MMAs) -> ~fp32-accurate output.
// DOTS: 0=none, 1=es+ed, 2=es only, 3=ed only  (per-head 64-col dot with avec)
#define BMM 128
#define BNN 128
#define BKC 32
#define LDP 36                 // padded row stride (floats): conflict-free frags
#define ABYTES (128 * LDP * 4) // 18432
#define STAGE  (2 * ABYTES)    // A + B per stage
#define SMEMSZ (2 * STAGE)     // 73728

template<int DOTS, int SPLIT>
__global__ void __launch_bounds__(256)
gemm_mma(const float* __restrict__ A, const float* __restrict__ B,
         const float* __restrict__ bias, const float* __restrict__ avec,
         float* __restrict__ C, float* __restrict__ es, float* __restrict__ ed,
         int M, int Nld) {
    extern __shared__ char smem[];
    uint32_t sb = smem_u32(smem);
    const int tid = threadIdx.x;
    const int wid = tid >> 5, lane = tid & 31;
    const int wm = wid & 3, wn = wid >> 2;      // warp tile: 32(M) x 64(N)
    const int g = lane >> 2, t = lane & 3;
    const int m0 = blockIdx.x * BMM;
    const int n0 = blockIdx.y * BNN;

    float d[2][8][4];
    #pragma unroll
    for (int ma = 0; ma < 2; ma++)
        #pragma unroll
        for (int na = 0; na < 8; na++)
            #pragma unroll
            for (int q = 0; q < 4; q++) d[ma][na][q] = 0.f;

    // ---- staging lambda-ish macro (A clamped rows, B always in range) ----
    const int sr = tid >> 3;          // 0..31 base row group (with j offset)
    const int sc = tid & 7;           // 16B column chunk
    #define STAGE_CHUNK(cc, buf)                                                   \
    do {                                                                           \
        uint32_t abase = sb + (buf) * STAGE;                                       \
        uint32_t bbase = abase + ABYTES;                                           \
        _Pragma("unroll")                                                          \
        for (int j = 0; j < 4; j++) {                                              \
            int r = sr + j * 32;                                                   \
            int row = m0 + r; if (row >= M) row = m0;                              \
            cp16(abase + r * (LDP * 4) + sc * 16,                                  \
                 &A[(size_t)row * 256 + (cc) * BKC + sc * 4]);                     \
        }                                                                          \
        _Pragma("unroll")                                                          \
        for (int j = 0; j < 4; j++) {                                              \
            int r = sr + j * 32;                                                   \
            cp16(bbase + r * (LDP * 4) + sc * 16,                                  \
                 &B[(size_t)(n0 + r) * 256 + (cc) * BKC + sc * 4]);                \
        }                                                                          \
        cp_commit();                                                               \
    } while (0)

    STAGE_CHUNK(0, 0);

    for (int c = 0; c < 8; c++) {
        int buf = c & 1;
        if (c < 7) {
            STAGE_CHUNK(c + 1, buf ^ 1);
            cp_wait<1>();
        } else {
            cp_wait<0>();
        }
        __syncthreads();

        const float* As = (const float*)(smem + buf * STAGE);
        const float* Bs = (const float*)(smem + buf * STAGE + ABYTES);

        #pragma unroll
        for (int ks = 0; ks < 4; ks++) {
            uint32_t aHi[2][4], aLo[2][4];
            #pragma unroll
            for (int ma = 0; ma < 2; ma++) {
                int r0 = wm * 32 + ma * 16 + g;
                int c0 = ks * 8 + t;
                float x0 = As[r0 * LDP + c0];
                float x1 = As[(r0 + 8) * LDP + c0];
                float x2 = As[r0 * LDP + c0 + 4];
                float x3 = As[(r0 + 8) * LDP + c0 + 4];
                aHi[ma][0] = f2tf32(x0); aHi[ma][1] = f2tf32(x1);
                aHi[ma][2] = f2tf32(x2); aHi[ma][3] = f2tf32(x3);
                if (SPLIT) {
                    aLo[ma][0] = f2tf32(x0 - __uint_as_float(aHi[ma][0]));
                    aLo[ma][1] = f2tf32(x1 - __uint_as_float(aHi[ma][1]));
                    aLo[ma][2] = f2tf32(x2 - __uint_as_float(aHi[ma][2]));
                    aLo[ma][3] = f2tf32(x3 - __uint_as_float(aHi[ma][3]));
                }
            }
            #pragma unroll
            for (int na = 0; na < 8; na++) {
                int br = wn * 64 + na * 8 + g;
                int c0 = ks * 8 + t;
                uint32_t bb[2];
                bb[0] = f2tf32(Bs[br * LDP + c0]);
                bb[1] = f2tf32(Bs[br * LDP + c0 + 4]);
                #pragma unroll
                for (int ma = 0; ma < 2; ma++) {
                    mma_tf32(d[ma][na], aHi[ma], bb);
                    if (SPLIT) mma_tf32(d[ma][na], aLo[ma], bb);
                }
            }
        }
        __syncthreads();
    }
    #undef STAGE_CHUNK

    // ---- epilogue: bias, fused dots, stores ----
    if (bias != nullptr) {
        #pragma unroll
        for (int na = 0; na < 8; na++)
            #pragma unroll
            for (int j = 0; j < 2; j++) {
                float bv = __ldg(&bias[n0 + wn * 64 + na * 8 + 2 * t + j]);
                d[0][na][j]     += bv;
                d[0][na][2 + j] += bv;
                d[1][na][j]     += bv;
                d[1][na][2 + j] += bv;
            }
    }

    int rbase = m0 + wm * 32;

    if (DOTS != 0) {
        int h = blockIdx.y * 2 + wn;   // head owned by this warp (BNN=128, HD=64)
        float e1[4] = {0.f, 0.f, 0.f, 0.f};
        float e2[4] = {0.f, 0.f, 0.f, 0.f};
        #pragma unroll
        for (int na = 0; na < 8; na++)
            #pragma unroll
            for (int j = 0; j < 2; j++) {
                int cw = na * 8 + 2 * t + j;
                float a1 = __ldg(&avec[h * 128 + cw]);
                float a2 = __ldg(&avec[h * 128 + 64 + cw]);
                e1[0] = fmaf(d[0][na][j], a1, e1[0]);
                e1[1] = fmaf(d[0][na][2 + j], a1, e1[1]);
                e1[2] = fmaf(d[1][na][j], a1, e1[2]);
                e1[3] = fmaf(d[1][na][2 + j], a1, e1[3]);
                e2[0] = fmaf(d[0][na][j], a2, e2[0]);
                e2[1] = fmaf(d[0][na][2 + j], a2, e2[1]);
                e2[2] = fmaf(d[1][na][j], a2, e2[2]);
                e2[3] = fmaf(d[1][na][2 + j], a2, e2[3]);
            }
        #pragma unroll
        for (int s = 0; s < 4; s++) {
            e1[s] += __shfl_xor_sync(0xffffffffu, e1[s], 1);
            e1[s] += __shfl_xor_sync(0xffffffffu, e1[s], 2);
            e2[s] += __shfl_xor_sync(0xffffffffu, e2[s], 1);
            e2[s] += __shfl_xor_sync(0xffffffffu, e2[s], 2);
        }
        if (t == 0) {
            int rows[4] = {rbase + g, rbase + 8 + g, rbase + 16 + g, rbase + 24 + g};
            #pragma unroll
            for (int s = 0; s < 4; s++) {
                if (rows[s] < M) {
                    if (DOTS == 1 || DOTS == 2) es[rows[s] * 4 + h] = e1[s];
                    if (DOTS == 1 || DOTS == 3) ed[rows[s] * 4 + h] = e2[s];
                }
            }
        }
    }

    if (C != nullptr) {
        #pragma unroll
        for (int ma = 0; ma < 2; ma++) {
            int r0 = rbase + ma * 16 + g;
            #pragma unroll
            for (int na = 0; na < 8; na++) {
                int col = n0 + wn * 64 + na * 8 + 2 * t;
                if (r0 < M) {
                    float2 v; v.x = d[ma][na][0]; v.y = d[ma][na][1];
                    *(float2*)&C[(size_t)r0 * Nld + col] = v;
                }
                if (r0 + 8 < M) {
                    float2 v; v.x = d[ma][na][2]; v.y = d[ma][na][3];
                    *(float2*)&C[(size_t)(r0 + 8) * Nld + col] = v;
                }
            }
        }
    }
}

// ---------------- weight repack: W[h][f][d] -> out[(h*64+d)][f] ----------------
__global__ void pack_headwise(const float* __restrict__ W, float* __restrict__ out) {
    int o = blockIdx.x * 256 + threadIdx.x;
    int n = o >> 8, f = o & 255;
    int h = n >> 6, dd = n & 63;
    out[o] = W[(h * 256 + f) * 64 + dd];
}

// ---------------- intra-turn GAT aggregation (deg 16) ----------------
__global__ __launch_bounds__(256)
void intra_agg(const float* __restrict__ Wh, const float* __restrict__ es,
               const float* __restrict__ ed, const float* __restrict__ ab,
               const int* __restrict__ src, float* __restrict__ x) {
    int d = blockIdx.x;
    int tid = threadIdx.x;
    __shared__ int   s_src[DEG_IN];
    __shared__ float se[NHEADS * DEG_IN];

    if (tid < DEG_IN) s_src[tid] = src[d * DEG_IN + tid];
    __syncthreads();

    if (tid < NHEADS * DEG_IN) {
        int i = tid & 15, h = tid >> 4;
        float e = es[s_src[i] * NHEADS + h] + ed[d * NHEADS + h] + ab[h];
        se[tid] = (e >= 0.f) ? e : ALPHA * e;
    }
    __syncthreads();

    if (tid < NHEADS) {
        float m = -1e30f;
        #pragma unroll
        for (int i = 0; i < DEG_IN; i++) m = fmaxf(m, se[tid * DEG_IN + i]);
        float s = 0.f;
        #pragma unroll
        for (int i = 0; i < DEG_IN; i++) {
            float ex = expf(se[tid * DEG_IN + i] - m);
            se[tid * DEG_IN + i] = ex;
            s += ex;
        }
        float inv = 1.f / fmaxf(s, 1e-9f);
        #pragma unroll
        for (int i = 0; i < DEG_IN; i++) se[tid * DEG_IN + i] *= inv;
    }
    __syncthreads();

    int h = tid >> 6;
    float acc = 0.f;
    #pragma unroll
    for (int i = 0; i < DEG_IN; i++)
        acc = fmaf(se[h * DEG_IN + i], Wh[s_src[i] * NHID + tid], acc);
    x[d * NHID + tid] = acc;
}

// ---------------- cross-turn GAT (counter + support fused) ----------------
__global__ __launch_bounds__(256)
void cross_agg(const float* __restrict__ Whp, const float* __restrict__ esP,
               const float* __restrict__ edX, const int* __restrict__ src_c,
               const int* __restrict__ src_s, float* __restrict__ hout) {
    int d = blockIdx.x;
    int tid = threadIdx.x;
    __shared__ int   sc[DEG_C], ss[DEG_C];
    __shared__ float se[2 * NHEADS * DEG_C];

    if (tid < DEG_C)           sc[tid]         = src_c[d * DEG_C + tid];
    else if (tid < 2 * DEG_C)  ss[tid - DEG_C] = src_s[d * DEG_C + (tid - DEG_C)];
    __syncthreads();

    if (tid < 64) {
        int which = tid >> 5;
        int tt = tid & 31;
        int i = tt & 7, h = tt >> 3;
        int s = which ? ss[i] : sc[i];
        float e = esP[s * NHEADS + h] + edX[d * NHEADS + h];
        se[tid] = (e >= 0.f) ? e : ALPHA * e;
    }
    __syncthreads();

    if (tid < 8) {
        float* ep = &se[(tid >> 2) * 32 + (tid & 3) * 8];
        float m = -1e30f;
        #pragma unroll
        for (int i = 0; i < DEG_C; i++) m = fmaxf(m, ep[i]);
        float s = 0.f;
        #pragma unroll
        for (int i = 0; i < DEG_C; i++) { float ex = expf(ep[i] - m); ep[i] = ex; s += ex; }
        float inv = 1.f / fmaxf(s, 1e-9f);
        #pragma unroll
        for (int i = 0; i < DEG_C; i++) ep[i] *= inv;
    }
    __syncthreads();

    int h = tid >> 6;
    float acc = 0.f;
    #pragma unroll
    for (int i = 0; i < DEG_C; i++)
        acc = fmaf(se[h * DEG_C + i], Whp[sc[i] * NHID + tid], acc);
    #pragma unroll
    for (int i = 0; i < DEG_C; i++)
        acc = fmaf(se[32 + h * DEG_C + i], Whp[ss[i] * NHID + tid], acc);
    hout[d * NHID + tid] = 0.5f * acc;
}

// ---------------- GRU elementwise ----------------
__global__ void gru_kernel(const float* __restrict__ gi, const float* __restrict__ gh,
                           const float* __restrict__ h, float* __restrict__ out) {
    int idx = blockIdx.x * 256 + threadIdx.x;
    int node = idx >> 8, c = idx & 255;
    const float* gip = gi + (size_t)node * 768;
    const float* ghp = gh + (size_t)node * 768;
    float r = 1.f / (1.f + expf(-(gip[c]       + ghp[c])));
    float z = 1.f / (1.f + expf(-(gip[256 + c] + ghp[256 + c])));
    float nn = tanhf(gip[512 + c] + r * ghp[512 + c]);
    out[idx] = (1.f - z) * nn + z * h[idx];
}

// ---------------- host launcher ----------------
extern "C" void kernel_launch(void* const* d_in, const int* in_sizes, int n_in,
                              void* d_out, int out_size) {
    const float* h_t      = (const float*)d_in[0];
    const float* h_prev   = (const float*)d_in[1];
    const float* W_intra  = (const float*)d_in[2];
    const float* b_intra  = (const float*)d_in[3];
    const float* a_intra  = (const float*)d_in[4];
    const float* ab_intra = (const float*)d_in[5];
    const float* W_cross  = (const float*)d_in[6];
    const float* a_cross  = (const float*)d_in[7];
    const float* W_ih     = (const float*)d_in[8];
    const float* W_hh     = (const float*)d_in[9];
    const float* b_ih     = (const float*)d_in[10];
    const float* b_hh     = (const float*)d_in[11];
    const int*   src_in   = (const int*)d_in[12];
    const int*   src_c    = (const int*)d_in[14];
    const int*   src_s    = (const int*)d_in[16];
    float* out = (float*)d_out;

    float *p_Wh, *p_x, *p_Whp, *p_h, *p_gi, *p_gh;
    float *p_pki, *p_pkc, *p_es, *p_ed, *p_esP, *p_edX;
    cudaGetSymbolAddress((void**)&p_Wh,  d_Wh);
    cudaGetSymbolAddress((void**)&p_x,   d_x);
    cudaGetSymbolAddress((void**)&p_Whp, d_Whp);
    cudaGetSymbolAddress((void**)&p_h,   d_h);
    cudaGetSymbolAddress((void**)&p_gi,  d_gi);
    cudaGetSymbolAddress((void**)&p_gh,  d_gh);
    cudaGetSymbolAddress((void**)&p_pki, d_pk_intra);
    cudaGetSymbolAddress((void**)&p_pkc, d_pk_cross);
    cudaGetSymbolAddress((void**)&p_es,  d_es);
    cudaGetSymbolAddress((void**)&p_ed,  d_ed);
    cudaGetSymbolAddress((void**)&p_esP, d_esP);
    cudaGetSymbolAddress((void**)&p_edX, d_edX);

    cudaFuncSetAttribute(gemm_mma<1,1>, cudaFuncAttributeMaxDynamicSharedMemorySize, SMEMSZ);
    cudaFuncSetAttribute(gemm_mma<2,1>, cudaFuncAttributeMaxDynamicSharedMemorySize, SMEMSZ);
    cudaFuncSetAttribute(gemm_mma<3,1>, cudaFuncAttributeMaxDynamicSharedMemorySize, SMEMSZ);
    cudaFuncSetAttribute(gemm_mma<0,0>, cudaFuncAttributeMaxDynamicSharedMemorySize, SMEMSZ);

    // 1. repack head-blocked weights into [n][k]
    pack_headwise<<<256, 256>>>(W_intra, p_pki);
    pack_headwise<<<256, 256>>>(W_cross, p_pkc);

    dim3 g2((NN + BMM - 1) / BMM, 2);   // 256-wide outputs
    dim3 g6((NN + BMM - 1) / BMM, 6);   // 768-wide outputs

    // 2. Wh = h_t @ W_intra^T + b  (split-A, fused es/ed)
    gemm_mma<1,1><<<g2, 256, SMEMSZ>>>(h_t, p_pki, b_intra, a_intra,
                                       p_Wh, p_es, p_ed, NN, NHID);
    // 3. Whp = h_prev @ W_cross^T  (split-A, fused esP)
    gemm_mma<2,1><<<g2, 256, SMEMSZ>>>(h_prev, p_pkc, nullptr, a_cross,
                                       p_Whp, p_esP, nullptr, NPREV, NHID);
    // 4. intra GAT -> x
    intra_agg<<<NN, 256>>>(p_Wh, p_es, p_ed, ab_intra, src_in, p_x);
    // 5. Whx dots only (C not stored; split-A, fused edX)
    gemm_mma<3,1><<<g2, 256, SMEMSZ>>>(p_x, p_pkc, nullptr, a_cross,
                                       nullptr, nullptr, p_edX, NN, NHID);
    // 6. cross GAT -> h
    cross_agg<<<NN, 256>>>(p_Whp, p_esP, p_edX, src_c, src_s, p_h);
    // 7. GRU gate GEMMs (plain tf32; W_ih/W_hh already [n][k])
    gemm_mma<0,0><<<g6, 256, SMEMSZ>>>(p_x, W_ih, b_ih, nullptr,
                                       p_gi, nullptr, nullptr, NN, 3 * NHID);
    gemm_mma<0,0><<<g6, 256, SMEMSZ>>>(p_h, W_hh, b_hh, nullptr,
                                       p_gh, nullptr, nullptr, NN, 3 * NHID);
    // 8. GRU elementwise -> out
    gru_kernel<<<NN, 256>>>(p_gi, p_gh, p_h, out);
}